// round 4
// baseline (speedup 1.0000x reference)
#include <cuda_runtime.h>
#include <mma.h>
#include <cstdint>

using namespace nvcuda;

#define NN 500000
#define ND 128
#define NH 64
#define NG 16384
#define NB 64                    // nodes per tile
#define TB 256                   // threads per CTA (8 warps)
#define GRID 304                 // persistent CTAs (2 per SM on 152-SM GB300)
#define NT ((NN + NB - 1) / NB)  // 7813 tiles

#define APITCH 132               // floats per X row in smem (conflict-free for frag loads)
#define WPITCH 132
#define CPITCH 68
#define A_FLOATS (NB * APITCH)           // 8448 floats = 33792 B per buffer
#define C_FLOATS (NB * CPITCH)           // 4352 floats = 17408 B
#define SMEM_DYN ((2 * A_FLOATS + C_FLOATS) * 4)   // 84992 B -> 2 CTAs/SM

__device__ int g_batch_is64;

// Zero graph-energy slots; detect batch dtype (int64 high-half at word NN-1 is 0).
__global__ void init_kernel(float* __restrict__ out, const int* __restrict__ bw) {
    int i = blockIdx.x * blockDim.x + threadIdx.x;
    if (i < NG) out[NN + i] = 0.0f;
    if (i == 0) g_batch_is64 = (bw[NN - 1] == 0) ? 1 : 0;
}

__device__ __forceinline__ uint4 rnd4(uint4 v) {   // fp32 -> tf32 round-to-nearest
    v.x += 0x1000u; v.y += 0x1000u; v.z += 0x1000u; v.w += 0x1000u;
    return v;
}

__device__ __forceinline__ uint32_t smem_u32(const void* p) {
    uint32_t a;
    asm("{ .reg .u64 t; cvta.to.shared.u64 t, %1; cvt.u32.u64 %0, t; }" : "=r"(a) : "l"(p));
    return a;
}

// Prefetch one 64-node X tile into smem via cp.async (zfill past NN).
__device__ __forceinline__ void prefetch_tile(int t, uint32_t dst,
                                              const float* __restrict__ X, int tid) {
    long node0 = (long)t * NB;
    #pragma unroll
    for (int q = 0; q < (NB * (ND / 4)) / TB; q++) {   // 8 x 16B per thread
        int idx = tid + q * TB;
        int row = idx >> 5;
        int c4  = idx & 31;
        long gn = node0 + row;
        const float* src = X + (gn < NN ? gn : (NN - 1)) * (long)ND + c4 * 4;
        unsigned sz = (gn < NN) ? 16u : 0u;
        asm volatile("cp.async.cg.shared.global [%0], [%1], 16, %2;"
                     :: "r"(dst + (unsigned)(row * APITCH * 4 + c4 * 16)),
                        "l"(src), "r"(sz));
    }
}

__global__ __launch_bounds__(TB, 2)
void mlp_kernel(const float* __restrict__ X,
                const float* __restrict__ aein,
                const void*  __restrict__ batch,
                const float* __restrict__ W1,
                const float* __restrict__ b1,
                const float* __restrict__ W2,
                const float* __restrict__ b2,
                float* __restrict__ out)
{
    extern __shared__ float sm[];
    float* A0 = sm;
    float* A1 = sm + A_FLOATS;
    float* Cs = sm + 2 * A_FLOATS;
    float* Ws = A1;                       // W1 staged in A1, consumed before 1st prefetch to A1
    __shared__ float b1s[NH], w2s[NH];

    const int tid = threadIdx.x;
    const int wid = tid >> 5;
    const int ct  = wid & 3;              // col-tile: 16 hidden cols
    const int ng  = wid >> 2;             // node half: 32 nodes

    // ---- Stage W1 once (tf32-rounded) into Ws ----
    #pragma unroll
    for (int i = tid; i < NH * (ND / 4); i += TB) {
        int row = i >> 5, c4 = i & 31;
        uint4 v = rnd4(*(const uint4*)(W1 + (size_t)row * ND + c4 * 4));
        *(uint4*)(Ws + row * WPITCH + c4 * 4) = v;
    }
    if (tid < NH) { b1s[tid] = b1[tid]; w2s[tid] = W2[tid]; }

    // ---- Prime prefetch: first tile -> A0 ----
    uint32_t a0u = smem_u32(A0), a1u = smem_u32(A1);
    prefetch_tile(blockIdx.x, a0u, X, tid);
    asm volatile("cp.async.commit_group;" ::: "memory");

    __syncthreads();

    // ---- Register-persistent W1 fragments (16 k-steps x 16 cols) ----
    wmma::fragment<wmma::matrix_b, 16, 16, 8, wmma::precision::tf32,
                   wmma::col_major> bf[16];
    #pragma unroll
    for (int k = 0; k < 16; k++)
        wmma::load_matrix_sync(bf[k], Ws + (ct * 16) * WPITCH + k * 8, WPITCH);
    __syncthreads();   // all Ws reads done before A1 gets overwritten by prefetch

    int buf = 0;
    for (int t = blockIdx.x; t < NT; t += GRID, buf ^= 1) {
        float* curA = buf ? A1 : A0;
        int tn = t + GRID;
        if (tn < NT) {
            prefetch_tile(tn, buf ? a0u : a1u, X, tid);
            asm volatile("cp.async.commit_group;" ::: "memory");
            asm volatile("cp.async.wait_group 1;" ::: "memory");
        } else {
            asm volatile("cp.async.wait_group 0;" ::: "memory");
        }
        __syncthreads();

        // ---- layer-1 GEMM: warp => 32 nodes x 16 cols ----
        wmma::fragment<wmma::accumulator, 16, 16, 8, float> acc[2];
        wmma::fill_fragment(acc[0], 0.0f);
        wmma::fill_fragment(acc[1], 0.0f);
        #pragma unroll
        for (int k = 0; k < 16; k++) {
            #pragma unroll
            for (int i = 0; i < 2; i++) {
                wmma::fragment<wmma::matrix_a, 16, 16, 8, wmma::precision::tf32,
                               wmma::row_major> a;
                wmma::load_matrix_sync(a, curA + (ng * 32 + i * 16) * APITCH + k * 8,
                                       APITCH);
                #pragma unroll
                for (int e = 0; e < a.num_elements; e++)   // tf32 RN in registers
                    a.x[e] = __uint_as_float(__float_as_uint(a.x[e]) + 0x1000u);
                wmma::mma_sync(acc[i], a, bf[k], acc[i]);
            }
        }
        #pragma unroll
        for (int i = 0; i < 2; i++)
            wmma::store_matrix_sync(Cs + (ng * 32 + i * 16) * CPITCH + ct * 16,
                                    acc[i], CPITCH, wmma::mem_row_major);
        __syncthreads();

        // ---- epilogue: silu + layer-2 + residual + segment atomic ----
        if (tid < NB) {
            long gn = (long)t * NB + tid;
            if (gn < NN) {
                float e = __ldg(b2) + __ldg(aein + gn);
                const float* crow = Cs + tid * CPITCH;
                #pragma unroll
                for (int j = 0; j < NH; j++) {
                    float h = crow[j] + b1s[j];
                    float s = h / (1.0f + __expf(-h));
                    e = fmaf(s, w2s[j], e);
                }
                out[gn] = e;
                int g;
                if (g_batch_is64) g = (int)((const long long*)batch)[gn];
                else              g = ((const int*)batch)[gn];
                atomicAdd(out + NN + g, e);
            }
        }
        __syncthreads();   // Cs reads done before next tile's C stores
    }
}

extern "C" void kernel_launch(void* const* d_in, const int* in_sizes, int n_in,
                              void* d_out, int out_size) {
    const float* X     = (const float*)d_in[0];
    const float* aein  = (const float*)d_in[1];
    const void*  batch = d_in[2];
    const float* W1    = (const float*)d_in[3];
    const float* b1    = (const float*)d_in[4];
    const float* W2    = (const float*)d_in[5];
    const float* b2    = (const float*)d_in[6];
    float* out = (float*)d_out;

    cudaFuncSetAttribute(mlp_kernel, cudaFuncAttributeMaxDynamicSharedMemorySize,
                         SMEM_DYN);

    init_kernel<<<(NG + 255) / 256, 256>>>(out, (const int*)batch);
    mlp_kernel<<<GRID, TB, SMEM_DYN>>>(X, aein, batch, W1, b1, W2, b2, out);
}

// round 5
// speedup vs baseline: 1.4620x; 1.4620x over previous
#include <cuda_runtime.h>
#include <mma.h>
#include <cstdint>

using namespace nvcuda;

#define NN 500000
#define ND 128
#define NH 64
#define NG 16384
#define NB 128                     // nodes per CTA
#define TB 256                     // 8 warps
#define NT ((NN + NB - 1) / NB)    // 3907 CTAs

#define APITCH 132                 // X smem row pitch (floats)
#define CPITCH 68                  // C smem row pitch (floats)
#define A_FLOATS (NB * APITCH)     // 16896 floats = 67584 B
#define SMEM_DYN (A_FLOATS * 4)    // 67.6 KB -> 3 CTAs/SM

__device__ int g_batch_is64;

// Zero graph-energy slots; detect batch dtype (word NN-1 is the zero int64
// high half iff batch stored as int64; nonzero if int32 sorted-random data).
__global__ void init_kernel(float* __restrict__ out, const int* __restrict__ bw) {
    int i = blockIdx.x * blockDim.x + threadIdx.x;
    if (i < NG) out[NN + i] = 0.0f;
    if (i == 0) g_batch_is64 = (bw[NN - 1] == 0) ? 1 : 0;
}

__device__ __forceinline__ uint4 rnd4(uint4 v) {   // fp32 -> tf32 RN on bits
    v.x += 0x1000u; v.y += 0x1000u; v.z += 0x1000u; v.w += 0x1000u;
    return v;
}

__global__ __launch_bounds__(TB, 3)
void mlp_kernel(const float* __restrict__ X,
                const float* __restrict__ aein,
                const void*  __restrict__ batch,
                const float* __restrict__ W1,
                const float* __restrict__ b1,
                const float* __restrict__ W2,
                const float* __restrict__ b2,
                float* __restrict__ out)
{
    extern __shared__ float sm[];
    float* As = sm;                      // X tile [128][APITCH]; later aliased as C
    __shared__ float b1s[NH], w2s[NH];

    const int tid   = threadIdx.x;
    const int wid   = tid >> 5;
    const int ct    = wid & 3;           // col-tile: 16 hidden cols
    const int ng    = wid >> 2;          // node-group: 64 nodes
    const long node0 = (long)blockIdx.x * NB;

    // ---- Stage X tile (coalesced float4), tf32-rounded; zero-pad past NN ----
    #pragma unroll
    for (int q = 0; q < (NB * (ND / 4)) / TB; q++) {   // 16 float4 per thread
        int idx = tid + q * TB;
        int row = idx >> 5;
        int c4  = idx & 31;
        long gn = node0 + row;
        uint4 v = make_uint4(0u, 0u, 0u, 0u);
        if (gn < NN) v = rnd4(*(const uint4*)(X + gn * (long)ND + c4 * 4));
        *(uint4*)(As + row * APITCH + c4 * 4) = v;
    }
    if (tid < NH) { b1s[tid] = b1[tid]; w2s[tid] = W2[tid]; }
    __syncthreads();

    // ---- Layer-1 GEMM: warp => 64 nodes x 16 cols, b-frags from global L1 ----
    wmma::fragment<wmma::accumulator, 16, 16, 8, float> acc[4];
    #pragma unroll
    for (int i = 0; i < 4; i++) wmma::fill_fragment(acc[i], 0.0f);

    const float* Wct = W1 + (size_t)(ct * 16) * ND;    // 16 rows of W1
    #pragma unroll
    for (int k = 0; k < ND / 8; k++) {
        wmma::fragment<wmma::matrix_b, 16, 16, 8, wmma::precision::tf32,
                       wmma::col_major> bf;
        // col_major: elem(k',n') at ptr[n'*ldm + k'] == W1[ct*16+n'][k*8+k']
        wmma::load_matrix_sync(bf, Wct + k * 8, ND);
        #pragma unroll
        for (int e = 0; e < bf.num_elements; e++)       // tf32 RN in registers
            bf.x[e] = __uint_as_float(__float_as_uint(bf.x[e]) + 0x1000u);
        #pragma unroll
        for (int i = 0; i < 4; i++) {
            wmma::fragment<wmma::matrix_a, 16, 16, 8, wmma::precision::tf32,
                           wmma::row_major> a;
            wmma::load_matrix_sync(a, As + (ng * 64 + i * 16) * APITCH + k * 8,
                                   APITCH);
            wmma::mma_sync(acc[i], a, bf, acc[i]);
        }
    }

    // ---- Spill C (aliases As; all A reads done) ----
    __syncthreads();
    float* Cs = As;                      // [128][CPITCH]
    #pragma unroll
    for (int i = 0; i < 4; i++)
        wmma::store_matrix_sync(Cs + (ng * 64 + i * 16) * CPITCH + ct * 16,
                                acc[i], CPITCH, wmma::mem_row_major);
    __syncthreads();

    // ---- Epilogue: all 256 threads; pair (node, col-half) ----
    {
        int node = tid >> 1;
        int half = tid & 1;
        long gn  = node0 + node;
        const float* crow = Cs + node * CPITCH + half * 32;
        const float* b1p  = b1s + half * 32;
        const float* w2p  = w2s + half * 32;
        float part = 0.0f;
        #pragma unroll
        for (int j = 0; j < 32; j++) {
            float h = crow[j] + b1p[j];
            float s = h * __frcp_rn(1.0f + __expf(-h));   // silu
            part = fmaf(s, w2p[j], part);
        }
        part += __shfl_xor_sync(0xFFFFFFFFu, part, 1);
        if (half == 0 && gn < NN) {
            float e = part + __ldg(b2) + __ldg(aein + gn);
            out[gn] = e;
            int g;
            if (g_batch_is64) g = (int)((const long long*)batch)[gn];
            else              g = ((const int*)batch)[gn];
            atomicAdd(out + NN + g, e);
        }
    }
}

extern "C" void kernel_launch(void* const* d_in, const int* in_sizes, int n_in,
                              void* d_out, int out_size) {
    const float* X     = (const float*)d_in[0];
    const float* aein  = (const float*)d_in[1];
    const void*  batch = d_in[2];
    const float* W1    = (const float*)d_in[3];
    const float* b1    = (const float*)d_in[4];
    const float* W2    = (const float*)d_in[5];
    const float* b2    = (const float*)d_in[6];
    float* out = (float*)d_out;

    cudaFuncSetAttribute(mlp_kernel, cudaFuncAttributeMaxDynamicSharedMemorySize,
                         SMEM_DYN);

    init_kernel<<<(NG + 255) / 256, 256>>>(out, (const int*)batch);
    mlp_kernel<<<NT, TB, SMEM_DYN>>>(X, aein, batch, W1, b1, W2, b2, out);
}

// round 6
// speedup vs baseline: 2.7612x; 1.8887x over previous
#include <cuda_runtime.h>
#include <cuda_bf16.h>
#include <mma.h>
#include <cstdint>

using namespace nvcuda;

#define NN 500000
#define ND 128
#define NH 64
#define NG 16384
#define NB 128                     // nodes per CTA
#define TB 256                     // 8 warps
#define NT ((NN + NB - 1) / NB)    // 3907 CTAs

#define APITCH 136                 // bf16 elems per A row (272B: ldmatrix conflict-free)
#define WPITCH 136
#define CPITCH 68                  // fp32 elems per C row (272B, aliases A exactly)
#define A_BYTES (NB * APITCH * 2)  // 34816
#define W_BYTES (NH * WPITCH * 2)  // 17408
#define SMEM_DYN (A_BYTES + W_BYTES)   // 52224 B -> 4 CTAs/SM

__device__ int g_batch_is64;

// Zero graph-energy slots; detect batch dtype (word NN-1 is the zero int64
// high half iff batch stored as int64).
__global__ void init_kernel(float* __restrict__ out, const int* __restrict__ bw) {
    int i = blockIdx.x * blockDim.x + threadIdx.x;
    if (i < NG) out[NN + i] = 0.0f;
    if (i == 0) g_batch_is64 = (bw[NN - 1] == 0) ? 1 : 0;
}

__device__ __forceinline__ uint2 cvt4_bf16(float4 f) {
    __nv_bfloat162 h0 = __floats2bfloat162_rn(f.x, f.y);  // .x in low half
    __nv_bfloat162 h1 = __floats2bfloat162_rn(f.z, f.w);
    uint2 u;
    u.x = *(uint32_t*)&h0;
    u.y = *(uint32_t*)&h1;
    return u;
}

__global__ __launch_bounds__(TB, 4)
void mlp_kernel(const float* __restrict__ X,
                const float* __restrict__ aein,
                const void*  __restrict__ batch,
                const float* __restrict__ W1,
                const float* __restrict__ b1,
                const float* __restrict__ W2,
                const float* __restrict__ b2,
                float* __restrict__ out)
{
    extern __shared__ char smraw[];
    __nv_bfloat16* As = (__nv_bfloat16*)smraw;             // [128][APITCH]
    __nv_bfloat16* Ws = (__nv_bfloat16*)(smraw + A_BYTES); // [64][WPITCH]
    float*         Cs = (float*)smraw;                     // aliases A after GEMM
    __shared__ float b1s[NH], w2s[NH];

    const int tid   = threadIdx.x;
    const int wid   = tid >> 5;
    const int ct    = wid & 3;            // col-tile: 16 hidden cols
    const int ng    = wid >> 2;           // node-group: 64 nodes
    const long node0 = (long)blockIdx.x * NB;

    // ---- Stage X tile: LDG.128 fp32 -> bf16(RN) -> STS.64 ----
    #pragma unroll
    for (int q = 0; q < (NB * (ND / 4)) / TB; q++) {   // 16 float4 per thread
        int idx = tid + q * TB;
        int row = idx >> 5;
        int c4  = idx & 31;
        long gn = node0 + row;
        uint2 u = make_uint2(0u, 0u);
        if (gn < NN) u = cvt4_bf16(*(const float4*)(X + gn * (long)ND + c4 * 4));
        *(uint2*)(As + row * APITCH + c4 * 4) = u;
    }
    // ---- Stage W1: bf16(RN) ----
    #pragma unroll
    for (int q = 0; q < (NH * (ND / 4)) / TB; q++) {   // 8 float4 per thread
        int idx = tid + q * TB;
        int row = idx >> 5;
        int c4  = idx & 31;
        uint2 u = cvt4_bf16(*(const float4*)(W1 + (size_t)row * ND + c4 * 4));
        *(uint2*)(Ws + row * WPITCH + c4 * 4) = u;
    }
    if (tid < NH) { b1s[tid] = b1[tid]; w2s[tid] = W2[tid]; }
    __syncthreads();

    // ---- Layer-1 GEMM: warp => 64 nodes x 16 cols, 8 K-steps of 16 ----
    wmma::fragment<wmma::accumulator, 16, 16, 16, float> acc[4];
    #pragma unroll
    for (int i = 0; i < 4; i++) wmma::fill_fragment(acc[i], 0.0f);

    #pragma unroll
    for (int k = 0; k < ND / 16; k++) {
        wmma::fragment<wmma::matrix_b, 16, 16, 16, __nv_bfloat16,
                       wmma::col_major> bf;
        // col_major: elem(k',n') at ptr[n'*ldm + k'] == W1[ct*16+n'][k*16+k']
        wmma::load_matrix_sync(bf, Ws + (ct * 16) * WPITCH + k * 16, WPITCH);
        #pragma unroll
        for (int i = 0; i < 4; i++) {
            wmma::fragment<wmma::matrix_a, 16, 16, 16, __nv_bfloat16,
                           wmma::row_major> a;
            wmma::load_matrix_sync(a, As + (ng * 64 + i * 16) * APITCH + k * 16,
                                   APITCH);
            wmma::mma_sync(acc[i], a, bf, acc[i]);
        }
    }

    // ---- Spill C (aliases A; all A reads done) ----
    __syncthreads();
    #pragma unroll
    for (int i = 0; i < 4; i++)
        wmma::store_matrix_sync(Cs + (ng * 64 + i * 16) * CPITCH + ct * 16,
                                acc[i], CPITCH, wmma::mem_row_major);
    __syncthreads();

    // ---- Epilogue: thread pair = (node, col-half) ----
    {
        int node = tid >> 1;
        int half = tid & 1;
        long gn  = node0 + node;
        const float* crow = Cs + node * CPITCH + half * 32;
        const float* b1p  = b1s + half * 32;
        const float* w2p  = w2s + half * 32;
        float part = 0.0f;
        #pragma unroll
        for (int j = 0; j < 32; j++) {
            float h = crow[j] + b1p[j];
            float s = h * __frcp_rn(1.0f + __expf(-h));   // silu
            part = fmaf(s, w2p[j], part);
        }
        part += __shfl_xor_sync(0xFFFFFFFFu, part, 1);
        if (half == 0 && gn < NN) {
            float e = part + __ldg(b2) + __ldg(aein + gn);
            out[gn] = e;
            int g;
            if (g_batch_is64) g = (int)((const long long*)batch)[gn];
            else              g = ((const int*)batch)[gn];
            atomicAdd(out + NN + g, e);
        }
    }
}

extern "C" void kernel_launch(void* const* d_in, const int* in_sizes, int n_in,
                              void* d_out, int out_size) {
    const float* X     = (const float*)d_in[0];
    const float* aein  = (const float*)d_in[1];
    const void*  batch = d_in[2];
    const float* W1    = (const float*)d_in[3];
    const float* b1    = (const float*)d_in[4];
    const float* W2    = (const float*)d_in[5];
    const float* b2    = (const float*)d_in[6];
    float* out = (float*)d_out;

    cudaFuncSetAttribute(mlp_kernel, cudaFuncAttributeMaxDynamicSharedMemorySize,
                         SMEM_DYN);

    init_kernel<<<(NG + 255) / 256, 256>>>(out, (const int*)batch);
    mlp_kernel<<<NT, TB, SMEM_DYN>>>(X, aein, batch, W1, b1, W2, b2, out);
}

// round 7
// speedup vs baseline: 3.0073x; 1.0891x over previous
#include <cuda_runtime.h>
#include <cuda_bf16.h>
#include <cstdint>

#define NN 500000
#define ND 128
#define NH 64
#define NG 16384
#define NB 128                     // nodes per CTA
#define TB 256                     // 8 warps
#define NT ((NN + NB - 1) / NB)    // 3907 CTAs

#define APITCH 136                 // bf16 elems per row (272B = 17*16B: LDSM conflict-free)
#define WPITCH 136
#define A_BYTES (NB * APITCH * 2)  // 34816
#define W_BYTES (NH * WPITCH * 2)  // 17408
#define SMEM_DYN (A_BYTES + W_BYTES)   // 52224 -> 4 CTAs/SM

__device__ int g_batch_is64;

// Zero graph-energy slots; detect batch dtype (word NN-1 is the zero int64
// high half iff batch stored as int64).
__global__ void init_kernel(float* __restrict__ out, const int* __restrict__ bw) {
    int i = blockIdx.x * blockDim.x + threadIdx.x;
    if (i < NG) out[NN + i] = 0.0f;
    if (i == 0) g_batch_is64 = (bw[NN - 1] == 0) ? 1 : 0;
}

__device__ __forceinline__ uint32_t smem_u32(const void* p) {
    uint32_t a;
    asm("{ .reg .u64 t; cvta.to.shared.u64 t, %1; cvt.u32.u64 %0, t; }" : "=r"(a) : "l"(p));
    return a;
}

// Pack 8 fp32 (two float4) -> 4 x bf16x2 (RN)
__device__ __forceinline__ uint4 pack8_bf16(float4 f0, float4 f1) {
    uint4 u;
    __nv_bfloat162 h;
    h = __floats2bfloat162_rn(f0.x, f0.y); u.x = *(uint32_t*)&h;
    h = __floats2bfloat162_rn(f0.z, f0.w); u.y = *(uint32_t*)&h;
    h = __floats2bfloat162_rn(f1.x, f1.y); u.z = *(uint32_t*)&h;
    h = __floats2bfloat162_rn(f1.z, f1.w); u.w = *(uint32_t*)&h;
    return u;
}

__device__ __forceinline__ void ldsm4(uint32_t* r, uint32_t addr) {
    asm volatile("ldmatrix.sync.aligned.m8n8.x4.shared.b16 {%0,%1,%2,%3}, [%4];"
                 : "=r"(r[0]), "=r"(r[1]), "=r"(r[2]), "=r"(r[3]) : "r"(addr));
}

__device__ __forceinline__ void mma16816(float* d, const uint32_t* a,
                                         uint32_t b0, uint32_t b1) {
    asm volatile(
        "mma.sync.aligned.m16n8k16.row.col.f32.bf16.bf16.f32 "
        "{%0,%1,%2,%3}, {%4,%5,%6,%7}, {%8,%9}, {%0,%1,%2,%3};"
        : "+f"(d[0]), "+f"(d[1]), "+f"(d[2]), "+f"(d[3])
        : "r"(a[0]), "r"(a[1]), "r"(a[2]), "r"(a[3]), "r"(b0), "r"(b1));
}

__device__ __forceinline__ float silu(float h) {
    return h * __frcp_rn(1.0f + __expf(-h));
}

__global__ __launch_bounds__(TB, 4)
void mlp_kernel(const float* __restrict__ X,
                const float* __restrict__ aein,
                const void*  __restrict__ batch,
                const float* __restrict__ W1,
                const float* __restrict__ b1,
                const float* __restrict__ W2,
                const float* __restrict__ b2,
                float* __restrict__ out)
{
    extern __shared__ char smraw[];
    __nv_bfloat16* As = (__nv_bfloat16*)smraw;
    __nv_bfloat16* Ws = (__nv_bfloat16*)(smraw + A_BYTES);
    __shared__ float b1s[NH], w2s[NH];

    const int tid  = threadIdx.x;
    const int lane = tid & 31;
    const int wid  = tid >> 5;
    const long node0 = (long)blockIdx.x * NB;

    // ---- Stage X tile: 2x LDG.128 -> bf16 -> 1x STS.128 (8 per thread) ----
    #pragma unroll
    for (int q = 0; q < 8; q++) {
        int idx = tid + q * TB;          // 2048 groups of 8 floats
        int row = idx >> 4;
        int g8  = idx & 15;
        long gn = node0 + row;
        uint4 u = make_uint4(0u, 0u, 0u, 0u);
        if (gn < NN) {
            const float4* p = (const float4*)(X + gn * (long)ND + g8 * 8);
            u = pack8_bf16(p[0], p[1]);
        }
        *(uint4*)(As + row * APITCH + g8 * 8) = u;
    }
    // ---- Stage W1: 4 STS.128 per thread ----
    #pragma unroll
    for (int q = 0; q < 4; q++) {
        int idx = tid + q * TB;          // 1024 groups
        int row = idx >> 4;
        int g8  = idx & 15;
        const float4* p = (const float4*)(W1 + (size_t)row * ND + g8 * 8);
        *(uint4*)(Ws + row * WPITCH + g8 * 8) = pack8_bf16(p[0], p[1]);
    }
    if (tid < NH) { b1s[tid] = b1[tid]; w2s[tid] = W2[tid]; }
    __syncthreads();

    const uint32_t smA = smem_u32(As), smW = smem_u32(Ws);
    const int g  = lane >> 2;
    const int tg = lane & 3;

    // ---- Load all A fragments for this warp's 16 nodes (8 k-steps) ----
    uint32_t af[8][4];
    {
        const int arow  = wid * 16 + (lane & 15);
        const int ahalf = (lane >> 4) * 8;
        #pragma unroll
        for (int k = 0; k < 8; k++)
            ldsm4(af[k], smA + (uint32_t)((arow * APITCH + k * 16 + ahalf) * 2));
    }

    // ---- GEMM + fused epilogue over 4 n-tile pairs ----
    float ps0 = 0.0f, ps1 = 0.0f;
    const int bline = (lane & 7) + ((lane >> 4) << 3);   // row within 16-row pair
    const int bkoff = (lane & 8) ? 8 : 0;
    #pragma unroll
    for (int jp = 0; jp < 4; jp++) {
        float acc0[4] = {0.f, 0.f, 0.f, 0.f};
        float acc1[4] = {0.f, 0.f, 0.f, 0.f};
        #pragma unroll
        for (int k = 0; k < 8; k++) {
            uint32_t bf[4];
            ldsm4(bf, smW + (uint32_t)(((jp * 16 + bline) * WPITCH + k * 16 + bkoff) * 2));
            mma16816(acc0, af[k], bf[0], bf[1]);
            mma16816(acc1, af[k], bf[2], bf[3]);
        }
        #pragma unroll
        for (int t = 0; t < 2; t++) {
            const float* ac = t ? acc1 : acc0;
            int c0 = (jp * 2 + t) * 8 + tg * 2;
            float2 bv = *(const float2*)(b1s + c0);
            float2 wv = *(const float2*)(w2s + c0);
            ps0 = fmaf(silu(ac[0] + bv.x), wv.x, ps0);
            ps0 = fmaf(silu(ac[1] + bv.y), wv.y, ps0);
            ps1 = fmaf(silu(ac[2] + bv.x), wv.x, ps1);
            ps1 = fmaf(silu(ac[3] + bv.y), wv.y, ps1);
        }
    }
    // reduce across the 4 threads sharing a row (tg = 0..3)
    ps0 += __shfl_xor_sync(0xFFFFFFFFu, ps0, 1);
    ps0 += __shfl_xor_sync(0xFFFFFFFFu, ps0, 2);
    ps1 += __shfl_xor_sync(0xFFFFFFFFu, ps1, 1);
    ps1 += __shfl_xor_sync(0xFFFFFFFFu, ps1, 2);

    if (tg == 0) {
        float bb = __ldg(b2);
        long gn0 = node0 + wid * 16 + g;
        long gn1 = gn0 + 8;
        if (gn0 < NN) {
            float e = ps0 + bb + __ldg(aein + gn0);
            out[gn0] = e;
            int gr;
            if (g_batch_is64) gr = (int)((const long long*)batch)[gn0];
            else              gr = ((const int*)batch)[gn0];
            atomicAdd(out + NN + gr, e);
        }
        if (gn1 < NN) {
            float e = ps1 + bb + __ldg(aein + gn1);
            out[gn1] = e;
            int gr;
            if (g_batch_is64) gr = (int)((const long long*)batch)[gn1];
            else              gr = ((const int*)batch)[gn1];
            atomicAdd(out + NN + gr, e);
        }
    }
}

extern "C" void kernel_launch(void* const* d_in, const int* in_sizes, int n_in,
                              void* d_out, int out_size) {
    const float* X     = (const float*)d_in[0];
    const float* aein  = (const float*)d_in[1];
    const void*  batch = d_in[2];
    const float* W1    = (const float*)d_in[3];
    const float* b1    = (const float*)d_in[4];
    const float* W2    = (const float*)d_in[5];
    const float* b2    = (const float*)d_in[6];
    float* out = (float*)d_out;

    cudaFuncSetAttribute(mlp_kernel, cudaFuncAttributeMaxDynamicSharedMemorySize,
                         SMEM_DYN);

    init_kernel<<<(NG + 255) / 256, 256>>>(out, (const int*)batch);
    mlp_kernel<<<NT, TB, SMEM_DYN>>>(X, aein, batch, W1, b1, W2, b2, out);
}